// round 13
// baseline (speedup 1.0000x reference)
#include <cuda_runtime.h>
#include <cuda_fp16.h>
#include <cstdint>

// Problem constants
#define BDIM  256          // B = BATCH*NBR
#define LDIM  64
#define DIN   64           // 2*K*U
#define HDIM  512
#define CDIM  1024         // 2*h
#define MOUT  144
#define BL    16384        // B*L
#define NS_STRIDE ((size_t)BL * HDIM)
#define OUT_FRE  0
#define OUT_FIM  524288
#define OUT_I    1048576

// ---------------- scratch ----------------
__device__ __align__(128) __half g_A0h[BDIM * LDIM * DIN];   // 2 MB
__device__ __align__(128) __half g_A0l[BDIM * LDIM * DIN];   // 2 MB
__device__ __align__(128) float g_Y [LDIM * BDIM * CDIM];    // 64 MB [n][b][o]
__device__ __align__(128) __half g_Mh[BL * HDIM];            // 16 MB [(b*64+n)][h]
__device__ __align__(128) __half g_Ml[BL * HDIM];            // 16 MB
__device__ __align__(128) float  g_S [BL * HDIM];            // 32 MB softplus (fp32)
__device__ __align__(128) float g_Y2[LDIM * BDIM * MOUT];    //  9 MB [n][b][c]
__device__ float g_pS [256 * CDIM];
__device__ float g_pS2[256 * CDIM];
__device__ float g_scale[CDIM];
__device__ float g_shift[CDIM];
__device__ float g_Ipart[BL];

// ================= helpers =================
__device__ __forceinline__ uint32_t smem_u32(const void* p) {
    uint32_t a;
    asm("{ .reg .u64 t; cvta.to.shared.u64 t, %1; cvt.u32.u64 %0, t; }" : "=r"(a) : "l"(p));
    return a;
}
__device__ __forceinline__ void ldmx4(uint32_t* r, uint32_t addr) {
    asm volatile("ldmatrix.sync.aligned.m8n8.x4.shared.b16 {%0,%1,%2,%3}, [%4];"
        : "=r"(r[0]), "=r"(r[1]), "=r"(r[2]), "=r"(r[3]) : "r"(addr));
}
__device__ __forceinline__ void mma_f16(float* c, const uint32_t* a,
                                        uint32_t b0, uint32_t b1) {
    asm volatile("mma.sync.aligned.m16n8k16.row.col.f32.f16.f16.f32 "
        "{%0,%1,%2,%3}, {%4,%5,%6,%7}, {%8,%9}, {%0,%1,%2,%3};"
        : "+f"(c[0]), "+f"(c[1]), "+f"(c[2]), "+f"(c[3])
        : "r"(a[0]), "r"(a[1]), "r"(a[2]), "r"(a[3]), "r"(b0), "r"(b1));
}
__device__ __forceinline__ void mma_f16acc(uint32_t* c, const uint32_t* a,
                                           uint32_t b0, uint32_t b1) {
    asm volatile("mma.sync.aligned.m16n8k16.row.col.f16.f16.f16.f16 "
        "{%0,%1}, {%2,%3,%4,%5}, {%6,%7}, {%0,%1};"
        : "+r"(c[0]), "+r"(c[1])
        : "r"(a[0]), "r"(a[1]), "r"(a[2]), "r"(a[3]), "r"(b0), "r"(b1));
}
#define CP_ASYNC16(dst, src) \
    asm volatile("cp.async.ca.shared.global [%0], [%1], 16;" :: "r"(dst), "l"(src))
#define CP_COMMIT() asm volatile("cp.async.commit_group;")
#define CP_WAIT0()  asm volatile("cp.async.wait_group 0;")

__device__ __forceinline__ uint2 cvt4h(float4 v) {
    __half2 a = __floats2half2_rn(v.x, v.y);
    __half2 b = __floats2half2_rn(v.z, v.w);
    uint2 r;
    r.x = *reinterpret_cast<uint32_t*>(&a);
    r.y = *reinterpret_cast<uint32_t*>(&b);
    return r;
}

// ================= fused GEMM + interleaved noise-MI blocks =================
// ilv == 0 : every block is a gemm block (gid = bid).
// ilv >  0 : bid % ilv == 0 -> gemm block gid = bid/ilv;
//            otherwise      -> noise block nid = bid - bid/ilv - 1.
// Interleaving distributes the short DRAM-bound noise CTAs THROUGHOUT the
// long tensor-bound gemm CTAs so the FIFO scheduler overlaps them (R11
// appended them and got a serial low-occupancy tail instead).
#define GBUF 49152
#define GSMEM (2 * GBUF)

__global__ __launch_bounds__(256) void gemm_mma(
    const float* __restrict__ Pw,
    const __half* __restrict__ Ah, const __half* __restrict__ Al,
    float* __restrict__ Y, int K, int M, int relu, int stats,
    int ilv, int mTiles,
    const float* __restrict__ Nz, int noiseAdd)
{
    extern __shared__ char sm[];
    const int bid = blockIdx.x;
    const int tid = threadIdx.x;

    int gid = bid;
    if (ilv) {
        if (bid % ilv) {
            // ---------------- noise-MI path ----------------
            const int nid = bid - bid / ilv - 1;
            const int sub = tid >> 7, tt = tid & 127;
            const int nb = nid * 2 + sub;
            const int n2 = nb >> 8, b2 = nb & 255;
            const size_t bl = (size_t)b2 * 64 + n2;
            const size_t mbase = bl * HDIM;
            const int d = tt * 4;

            uint2 hv = *(const uint2*)&g_Mh[mbase + d];
            uint2 lv = *(const uint2*)&g_Ml[mbase + d];
            float4 sv = *(const float4*)&g_S[mbase + d];
            float4 z0 = *(const float4*)&Nz[mbase + d];
            float4 z1 = *(const float4*)&Nz[mbase + d + NS_STRIDE];
            float4 z2 = *(const float4*)&Nz[mbase + d + 2 * NS_STRIDE];
            float4 z3 = *(const float4*)&Nz[mbase + d + 3 * NS_STRIDE];

            __half2 h01 = *reinterpret_cast<__half2*>(&hv.x);
            __half2 h23 = *reinterpret_cast<__half2*>(&hv.y);
            __half2 l01 = *reinterpret_cast<__half2*>(&lv.x);
            __half2 l23 = *reinterpret_cast<__half2*>(&lv.y);
            float m[4] = { __low2float(h01) + __low2float(l01),
                           __high2float(h01) + __high2float(l01),
                           __low2float(h23) + __low2float(l23),
                           __high2float(h23) + __high2float(l23) };
            float s[4] = { sv.x, sv.y, sv.z, sv.w };
            float a0[4] = { z0.x, z0.y, z0.z, z0.w };
            float a1[4] = { z1.x, z1.y, z1.z, z1.w };
            float a2[4] = { z2.x, z2.y, z2.z, z2.w };
            float a3[4] = { z3.x, z3.y, z3.z, z3.w };

            float local = 0.f;
#pragma unroll
            for (int i = 0; i < 4; i++) {
                float S1 = (a0[i] + a1[i] + a2[i] + a3[i]) * 0.25f;
                float S2 = (a0[i] * a0[i] + a1[i] * a1[i] +
                            a2[i] * a2[i] + a3[i] * a3[i]) * 0.25f;
                local += 0.5f * m[i] * m[i] - __logf(s[i]) + m[i] * s[i] * S1
                       + 0.5f * (s[i] * s[i] - 1.0f) * S2;
            }
            float* sh = (float*)sm;
            sh[tid] = local;
            __syncthreads();
            for (int off = 64; off; off >>= 1) {
                if (tt < off) sh[tid] += sh[tid + off];
                __syncthreads();
            }
            if (tt == 0) {
                if (noiseAdd) g_Ipart[bl] += sh[tid];
                else          g_Ipart[bl]  = sh[tid];
            }
            return;
        }
        gid = bid / ilv;
    }

    // ---------------- GEMM path ----------------
    const int wid = tid >> 5, lid = tid & 31;
    const int m0 = (gid % mTiles) * 128;
    const int rem = gid / mTiles;
    const int by = rem & 1;
    const int n = rem >> 1;
    const int b0 = by * 128;
    const int nchunk = K >> 6;
    uint32_t sb = smem_u32(sm);

    const int r0 = tid >> 4, c4 = tid & 15;
    const int cswP = (((c4 >> 1) ^ (r0 & 7)) << 4) + (c4 & 1) * 8;
    const int ac = c4 & 7;
    const int aregion = (c4 < 8) ? 0 : 16384;
    const int cswA = ((ac ^ (r0 & 7)) << 4);
    const __half* Asrc = (c4 < 8) ? Ah : Al;

    const int lr  = (lid & 7) + ((lid >> 3) & 1) * 8;
    const int kch = lid >> 4;
    const int warp_b = wid >> 2, warp_o = wid & 3;
    int rowA128[4], r7A[4], rowB128[2], r7B[2];
#pragma unroll
    for (int mm = 0; mm < 4; mm++) {
        int r = warp_b * 64 + mm * 16 + lr;
        rowA128[mm] = r * 128; r7A[mm] = r & 7;
    }
#pragma unroll
    for (int g = 0; g < 2; g++) {
        int r = warp_o * 32 + g * 16 + lr;
        rowB128[g] = r * 128; r7B[g] = r & 7;
    }

    float acc[4][4][4];
    uint32_t acc16[4][4][2];
#pragma unroll
    for (int i = 0; i < 4; i++)
#pragma unroll
        for (int j = 0; j < 4; j++) {
#pragma unroll
            for (int q = 0; q < 4; q++) acc[i][j][q] = 0.f;
            acc16[i][j][0] = 0u; acc16[i][j][1] = 0u;
        }

    float4 stP[8];

    // prologue: chunk 0
#pragma unroll
    for (int j = 0; j < 8; j++) {
        int row = j * 16 + r0;
        const void* src = &Asrc[((size_t)(b0 + row) * 64 + n) * K + ac * 8];
        CP_ASYNC16(sb + aregion + row * 128 + cswA, src);
    }
    CP_COMMIT();
#pragma unroll
    for (int j = 0; j < 8; j++) {
        int row = j * 16 + r0;
        stP[j] = *(const float4*)&Pw[((size_t)n * M + m0 + row) * K + c4 * 4];
    }
#pragma unroll
    for (int j = 0; j < 8; j++) {
        int row = j * 16 + r0;
        *(uint2*)(sm + 32768 + row * 128 + cswP) = cvt4h(stP[j]);
    }
    CP_WAIT0();
    __syncthreads();

    for (int c = 0; c < nchunk; c++) {
        if (c + 1 < nchunk) {
            int k0 = (c + 1) << 6;
            uint32_t bdst = sb + ((c + 1) & 1) * GBUF;
#pragma unroll
            for (int j = 0; j < 8; j++) {
                int row = j * 16 + r0;
                const void* src = &Asrc[((size_t)(b0 + row) * 64 + n) * K + k0 + ac * 8];
                CP_ASYNC16(bdst + aregion + row * 128 + cswA, src);
            }
            CP_COMMIT();
#pragma unroll
            for (int j = 0; j < 8; j++) {
                int row = j * 16 + r0;
                stP[j] = *(const float4*)&Pw[((size_t)n * M + m0 + row) * K + k0 + c4 * 4];
            }
        }

        uint32_t ub = sb + (c & 1) * GBUF;
#pragma unroll
        for (int kk = 0; kk < 4; kk++) {
            uint32_t ah[4][4], al[4][4], bh[2][4];
            int ksel = kk * 2 + kch;
#pragma unroll
            for (int mm = 0; mm < 4; mm++)
                ldmx4(ah[mm], ub + rowA128[mm] + ((ksel ^ r7A[mm]) << 4));
#pragma unroll
            for (int mm = 0; mm < 4; mm++)
                ldmx4(al[mm], ub + 16384 + rowA128[mm] + ((ksel ^ r7A[mm]) << 4));
#pragma unroll
            for (int g = 0; g < 2; g++)
                ldmx4(bh[g], ub + 32768 + rowB128[g] + ((ksel ^ r7B[g]) << 4));
#pragma unroll
            for (int mm = 0; mm < 4; mm++)
#pragma unroll
                for (int nn = 0; nn < 4; nn++) {
                    int g = nn >> 1, s = nn & 1;
                    mma_f16(acc[mm][nn], ah[mm], bh[g][s], bh[g][s + 2]);
                    mma_f16acc(acc16[mm][nn], al[mm], bh[g][s], bh[g][s + 2]);
                }
        }

        if (c + 1 < nchunk) {
            char* buf = sm + ((c + 1) & 1) * GBUF;
#pragma unroll
            for (int j = 0; j < 8; j++) {
                int row = j * 16 + r0;
                *(uint2*)(buf + 32768 + row * 128 + cswP) = cvt4h(stP[j]);
            }
            CP_WAIT0();
        }
        __syncthreads();
    }

    // merge f16 correction + relu
#pragma unroll
    for (int i = 0; i < 4; i++)
#pragma unroll
        for (int j = 0; j < 4; j++) {
            __half2 p0 = *reinterpret_cast<__half2*>(&acc16[i][j][0]);
            __half2 p1 = *reinterpret_cast<__half2*>(&acc16[i][j][1]);
            acc[i][j][0] += __low2float(p0);
            acc[i][j][1] += __high2float(p0);
            acc[i][j][2] += __low2float(p1);
            acc[i][j][3] += __high2float(p1);
        }
    if (relu) {
#pragma unroll
        for (int i = 0; i < 4; i++)
#pragma unroll
            for (int j = 0; j < 4; j++)
#pragma unroll
                for (int q = 0; q < 4; q++) acc[i][j][q] = fmaxf(acc[i][j][q], 0.f);
    }

#pragma unroll
    for (int mm = 0; mm < 4; mm++) {
        int bg = b0 + warp_b * 64 + mm * 16 + (lid >> 2);
#pragma unroll
        for (int nn = 0; nn < 4; nn++) {
            int og = m0 + warp_o * 32 + nn * 8 + (lid & 3) * 2;
            float2 v01 = make_float2(acc[mm][nn][0], acc[mm][nn][1]);
            float2 v23 = make_float2(acc[mm][nn][2], acc[mm][nn][3]);
            *(float2*)&Y[((size_t)n * 256 + bg) * M + og] = v01;
            *(float2*)&Y[((size_t)n * 256 + bg + 8) * M + og] = v23;
        }
    }

    // fused BN partial stats (deterministic per-slot)
    if (stats) {
        float s1[8], s2v[8];
#pragma unroll
        for (int k = 0; k < 8; k++) { s1[k] = 0.f; s2v[k] = 0.f; }
#pragma unroll
        for (int nn = 0; nn < 4; nn++)
#pragma unroll
            for (int q = 0; q < 2; q++) {
                int k = nn * 2 + q;
#pragma unroll
                for (int mm = 0; mm < 4; mm++) {
                    float v0 = acc[mm][nn][q], v1 = acc[mm][nn][q + 2];
                    s1[k] += v0 + v1;
                    s2v[k] += v0 * v0 + v1 * v1;
                }
            }
#pragma unroll
        for (int k = 0; k < 8; k++)
#pragma unroll
            for (int msk = 4; msk <= 16; msk <<= 1) {
                s1[k]  += __shfl_xor_sync(0xFFFFFFFFu, s1[k],  msk);
                s2v[k] += __shfl_xor_sync(0xFFFFFFFFu, s2v[k], msk);
            }
        if ((lid >> 2) == 0) {
            int slot = (by * 64 + n) * 2 + warp_b;
#pragma unroll
            for (int nn = 0; nn < 4; nn++)
#pragma unroll
                for (int q = 0; q < 2; q++) {
                    int ch = m0 + warp_o * 32 + nn * 8 + (lid & 3) * 2 + q;
                    g_pS [slot * CDIM + ch] = s1[nn * 2 + q];
                    g_pS2[slot * CDIM + ch] = s2v[nn * 2 + q];
                }
        }
    }
}

// ================= pre/post kernels =================
__global__ void build_a0(const float* __restrict__ Hre, const float* __restrict__ Him) {
    int b = blockIdx.x, t = threadIdx.x;
    const float* hr = Hre + (size_t)b * 2048;
    const float* hi = Him + (size_t)b * 2048;
    size_t dbase = (size_t)b * 4096;
#pragma unroll
    for (int j = 0; j < 8; j++) {
        int idx = t + j * 256;
        int n = idx >> 5, d = idx & 31;
        float v0 = hr[idx], v1 = hi[idx];
        __half h0 = __float2half_rn(v0);
        __half h1 = __float2half_rn(v1);
        g_A0h[dbase + n * 64 + d]      = h0;
        g_A0h[dbase + n * 64 + 32 + d] = h1;
        g_A0l[dbase + n * 64 + d]      = __float2half_rn(v0 - __half2float(h0));
        g_A0l[dbase + n * 64 + 32 + d] = __float2half_rn(v1 - __half2float(h1));
    }
}

// slot-parallel BN finalize: 32 blocks x 256 thr
__global__ void bn_finalize(const float* __restrict__ w, const float* __restrict__ bb) {
    int c = blockIdx.x * 32 + (threadIdx.x & 31);
    int g = threadIdx.x >> 5;
    float s = 0.f, s2 = 0.f;
#pragma unroll
    for (int i = 0; i < 32; i++) {
        int sl = g * 32 + i;
        s  += g_pS [sl * CDIM + c];
        s2 += g_pS2[sl * CDIM + c];
    }
    __shared__ float a1[8][32], a2[8][32];
    a1[g][threadIdx.x & 31] = s;
    a2[g][threadIdx.x & 31] = s2;
    __syncthreads();
    if (g == 0) {
        float ts = 0.f, ts2 = 0.f;
#pragma unroll
        for (int j = 0; j < 8; j++) { ts += a1[j][threadIdx.x & 31]; ts2 += a2[j][threadIdx.x & 31]; }
        float mean = ts / (float)BL;
        float var  = ts2 / (float)BL - mean * mean;
        float sc = w[c] * rsqrtf(var + 1e-5f);
        g_scale[c] = sc;
        g_shift[c] = bb[c] - mean * sc;
    }
}

// elementwise BN-apply: m -> Mh/Ml (fp16 hi/lo), softplus(std) -> S (fp32)
__global__ void bn_apply(const float* __restrict__ Y) {
    int nb = blockIdx.x, t = threadIdx.x;   // 128 threads
    int n = nb >> 8, b = nb & 255;
    size_t ybase = (size_t)nb * CDIM;
    size_t mbase = ((size_t)b * 64 + n) * HDIM;
    int d = t * 4;

    float4 ym = *(const float4*)&Y[ybase + d];
    float4 ys = *(const float4*)&Y[ybase + HDIM + d];
    float4 scm = *(const float4*)&g_scale[d];
    float4 shm = *(const float4*)&g_shift[d];
    float4 scs = *(const float4*)&g_scale[HDIM + d];
    float4 shs = *(const float4*)&g_shift[HDIM + d];

    float m[4] = { scm.x * ym.x + shm.x, scm.y * ym.y + shm.y,
                   scm.z * ym.z + shm.z, scm.w * ym.w + shm.w };
    float x[4] = { scs.x * ys.x + shs.x, scs.y * ys.y + shs.y,
                   scs.z * ys.z + shs.z, scs.w * ys.w + shs.w };
    float4 sv;
    float* sp = &sv.x;
    float lo[4];
#pragma unroll
    for (int i = 0; i < 4; i++) {
        sp[i] = fmaxf(x[i], 0.f) + log1pf(__expf(-fabsf(x[i]))) + 1e-10f;
        __half mh = __float2half_rn(m[i]);
        lo[i] = m[i] - __half2float(mh);
        m[i] = __half2float(mh);
    }
    __half2 mh01 = __floats2half2_rn(m[0], m[1]);
    __half2 mh23 = __floats2half2_rn(m[2], m[3]);
    __half2 ml01 = __floats2half2_rn(lo[0], lo[1]);
    __half2 ml23 = __floats2half2_rn(lo[2], lo[3]);
    uint2 hv, lv;
    hv.x = *reinterpret_cast<uint32_t*>(&mh01);
    hv.y = *reinterpret_cast<uint32_t*>(&mh23);
    lv.x = *reinterpret_cast<uint32_t*>(&ml01);
    lv.y = *reinterpret_cast<uint32_t*>(&ml23);
    *(uint2*)&g_Mh[mbase + d] = hv;
    *(uint2*)&g_Ml[mbase + d] = lv;
    *(float4*)&g_S[mbase + d] = sv;
}

// merged pn + final + I-sum
__global__ void epilogue_kernel(float* __restrict__ out) {
    int b = blockIdx.x, t = threadIdx.x;
    __shared__ float v[64][72];
    __shared__ float pk[64];
    __shared__ float Pn[8];
    __shared__ float mult[64][8];

    for (int idx = t; idx < 64 * 72; idx += 128) {
        int n = idx / 72, c = idx % 72;
        v[n][c] = g_Y2[((size_t)(n * 256 + b)) * MOUT + c];
    }
    __syncthreads();
    if (t < 64) {
        int k = t & 7, j = t >> 3;
        float s = 0.f;
#pragma unroll
        for (int n = j; n < 64; n += 8) { float x = v[n][64 + k]; s += x * x; }
        pk[t] = s;
    }
    __syncthreads();
    if (t < 8) {
        float tot = 0.f;
#pragma unroll
        for (int j = 0; j < 8; j++) tot += pk[j * 8 + t];
        Pn[t] = sqrtf(tot);
    }
    __syncthreads();
    for (int idx = t; idx < 512; idx += 128) {
        int n = idx >> 3, k = idx & 7;
        float ss = 0.f;
#pragma unroll
        for (int u = 0; u < 4; u++) {
            float a = v[n][k * 4 + u], c2 = v[n][32 + k * 4 + u];
            ss += a * a + c2 * c2;
        }
        mult[n][k] = v[n][64 + k] / Pn[k] * 8.0f / sqrtf(ss);  // sqrt(L)=8
    }
    __syncthreads();
    for (int idx = t; idx < 64 * 32; idx += 128) {
        int n = idx >> 5, c = idx & 31;
        size_t obase = ((size_t)b * 64 + n) * 32;
        float mlt = mult[n][c >> 2];
        out[OUT_FRE + obase + c] = v[n][c] * mlt;
        out[OUT_FIM + obase + c] = v[n][32 + c] * mlt;
    }
    if (t < 64) pk[t] = g_Ipart[(size_t)b * 64 + t];
    __syncthreads();
    if (t == 0) {
        float s = 0.f;
#pragma unroll
        for (int n = 0; n < 64; n++) s += pk[n];
        out[OUT_I + b] = s;
    }
}

// ================= launch =================
extern "C" void kernel_launch(void* const* d_in, const int* in_sizes, int n_in,
                              void* d_out, int out_size) {
    const float* Hre = (const float*)d_in[0];
    const float* Him = (const float*)d_in[1];
    const float* P0  = (const float*)d_in[2];
    const float* P1  = (const float*)d_in[3];
    const float* P2  = (const float*)d_in[4];
    const float* w0  = (const float*)d_in[5];
    const float* b0  = (const float*)d_in[6];
    const float* w1  = (const float*)d_in[7];
    const float* b1  = (const float*)d_in[8];
    const float* nz0 = (const float*)d_in[9];
    const float* nz1 = (const float*)d_in[10];
    float* out = (float*)d_out;

    float *Yp, *Y2p;
    __half *A0h, *A0l, *Mh, *Ml;
    cudaGetSymbolAddress((void**)&A0h, g_A0h);
    cudaGetSymbolAddress((void**)&A0l, g_A0l);
    cudaGetSymbolAddress((void**)&Yp,  g_Y);
    cudaGetSymbolAddress((void**)&Mh,  g_Mh);
    cudaGetSymbolAddress((void**)&Ml,  g_Ml);
    cudaGetSymbolAddress((void**)&Y2p, g_Y2);

    cudaFuncSetAttribute(gemm_mma, cudaFuncAttributeMaxDynamicSharedMemorySize, GSMEM);

    // layer 0: K=64, no noise attached (ilv=0 -> all gemm blocks)
    build_a0<<<BDIM, 256>>>(Hre, Him);
    gemm_mma<<<1024, 256, GSMEM>>>(P0, A0h, A0l, Yp, DIN, CDIM, 1, 1,
                                   0, 8, nullptr, 0);
    bn_finalize<<<32, 256>>>(w0, b0);
    bn_apply<<<BL, 128>>>(Yp);

    // layer 1: K=512; noise0 MI blocks INTERLEAVED (1 gemm per 9 blocks)
    // 9216 = 1024 gemm + 8192 noise
    gemm_mma<<<9216, 256, GSMEM>>>(P1, Mh, Ml, Yp, HDIM, CDIM, 1, 1,
                                   9, 8, nz0, 0);
    bn_finalize<<<32, 256>>>(w1, b1);
    bn_apply<<<BL, 128>>>(Yp);

    // layer 2: K=512, channels 0..127 only; noise1 interleaved (1 per 65)
    // 8320 = 128 gemm + 8192 noise
    gemm_mma<<<8320, 256, GSMEM>>>(P2, Mh, Ml, Y2p, HDIM, MOUT, 0, 0,
                                   65, 1, nz1, 1);

    // merged epilogue
    epilogue_kernel<<<BDIM, 128>>>(out);
}

// round 14
// speedup vs baseline: 1.4090x; 1.4090x over previous
#include <cuda_runtime.h>
#include <cuda_fp16.h>
#include <cstdint>

// Problem constants
#define BDIM  256          // B = BATCH*NBR
#define LDIM  64
#define DIN   64           // 2*K*U
#define HDIM  512
#define CDIM  1024         // 2*h
#define MOUT  144
#define BL    16384        // B*L
#define NS_STRIDE ((size_t)BL * HDIM)
#define OUT_FRE  0
#define OUT_FIM  524288
#define OUT_I    1048576

// ---------------- scratch ----------------
__device__ __align__(128) __half g_A0h[BDIM * LDIM * DIN];   // 2 MB
__device__ __align__(128) __half g_A0l[BDIM * LDIM * DIN];   // 2 MB
__device__ __align__(128) float g_Y [LDIM * BDIM * CDIM];    // 64 MB [n][b][o]
__device__ __align__(128) __half g_Mh[BL * HDIM];            // 16 MB [(b*64+n)][h]
__device__ __align__(128) __half g_Ml[BL * HDIM];            // 16 MB
__device__ __align__(128) float  g_S [BL * HDIM];            // 32 MB softplus (fp32)
__device__ __align__(128) float g_Y2[LDIM * BDIM * MOUT];    //  9 MB [n][b][c]
__device__ float g_pS [256 * CDIM];
__device__ float g_pS2[256 * CDIM];
__device__ float g_scale[CDIM];
__device__ float g_shift[CDIM];
__device__ float g_Ipart[BL];

// ================= helpers =================
__device__ __forceinline__ uint32_t smem_u32(const void* p) {
    uint32_t a;
    asm("{ .reg .u64 t; cvta.to.shared.u64 t, %1; cvt.u32.u64 %0, t; }" : "=r"(a) : "l"(p));
    return a;
}
__device__ __forceinline__ void ldmx4(uint32_t* r, uint32_t addr) {
    asm volatile("ldmatrix.sync.aligned.m8n8.x4.shared.b16 {%0,%1,%2,%3}, [%4];"
        : "=r"(r[0]), "=r"(r[1]), "=r"(r[2]), "=r"(r[3]) : "r"(addr));
}
__device__ __forceinline__ void mma_f16(float* c, const uint32_t* a,
                                        uint32_t b0, uint32_t b1) {
    asm volatile("mma.sync.aligned.m16n8k16.row.col.f32.f16.f16.f32 "
        "{%0,%1,%2,%3}, {%4,%5,%6,%7}, {%8,%9}, {%0,%1,%2,%3};"
        : "+f"(c[0]), "+f"(c[1]), "+f"(c[2]), "+f"(c[3])
        : "r"(a[0]), "r"(a[1]), "r"(a[2]), "r"(a[3]), "r"(b0), "r"(b1));
}
__device__ __forceinline__ void mma_f16acc(uint32_t* c, const uint32_t* a,
                                           uint32_t b0, uint32_t b1) {
    asm volatile("mma.sync.aligned.m16n8k16.row.col.f16.f16.f16.f16 "
        "{%0,%1}, {%2,%3,%4,%5}, {%6,%7}, {%0,%1};"
        : "+r"(c[0]), "+r"(c[1])
        : "r"(a[0]), "r"(a[1]), "r"(a[2]), "r"(a[3]), "r"(b0), "r"(b1));
}
#define CP_ASYNC16(dst, src) \
    asm volatile("cp.async.ca.shared.global [%0], [%1], 16;" :: "r"(dst), "l"(src))
#define CP_COMMIT() asm volatile("cp.async.commit_group;")
#define CP_WAIT0()  asm volatile("cp.async.wait_group 0;")

__device__ __forceinline__ uint2 cvt4h(float4 v) {
    __half2 a = __floats2half2_rn(v.x, v.y);
    __half2 b = __floats2half2_rn(v.z, v.w);
    uint2 r;
    r.x = *reinterpret_cast<uint32_t*>(&a);
    r.y = *reinterpret_cast<uint32_t*>(&b);
    return r;
}

// ================= tensor-core batched GEMM (R10 structure) =================
// 2-term fp16: Ph*Ahi (f32 acc) + Ph*Alo (f16 acc)
// Y[n][b][o] = sum_d P[n][o][d] * Act[(b*64+n)][d]
// CTA tile 128b x 128o x 64k; 8 warps (2b x 4o).
#define GBUF 49152
#define GSMEM (2 * GBUF)

__global__ __launch_bounds__(256) void gemm_mma(
    const float* __restrict__ Pw,
    const __half* __restrict__ Ah, const __half* __restrict__ Al,
    float* __restrict__ Y, int K, int M, int relu, int stats, int mTiles)
{
    extern __shared__ char sm[];
    const int bid = blockIdx.x;
    const int tid = threadIdx.x;
    const int wid = tid >> 5, lid = tid & 31;
    const int m0 = (bid % mTiles) * 128;
    const int rem = bid / mTiles;
    const int by = rem & 1;
    const int n = rem >> 1;
    const int b0 = by * 128;
    const int nchunk = K >> 6;
    uint32_t sb = smem_u32(sm);

    const int r0 = tid >> 4, c4 = tid & 15;
    const int cswP = (((c4 >> 1) ^ (r0 & 7)) << 4) + (c4 & 1) * 8;
    const int ac = c4 & 7;
    const int aregion = (c4 < 8) ? 0 : 16384;
    const int cswA = ((ac ^ (r0 & 7)) << 4);
    const __half* Asrc = (c4 < 8) ? Ah : Al;

    const int lr  = (lid & 7) + ((lid >> 3) & 1) * 8;
    const int kch = lid >> 4;
    const int warp_b = wid >> 2, warp_o = wid & 3;
    int rowA128[4], r7A[4], rowB128[2], r7B[2];
#pragma unroll
    for (int mm = 0; mm < 4; mm++) {
        int r = warp_b * 64 + mm * 16 + lr;
        rowA128[mm] = r * 128; r7A[mm] = r & 7;
    }
#pragma unroll
    for (int g = 0; g < 2; g++) {
        int r = warp_o * 32 + g * 16 + lr;
        rowB128[g] = r * 128; r7B[g] = r & 7;
    }

    float acc[4][4][4];
    uint32_t acc16[4][4][2];
#pragma unroll
    for (int i = 0; i < 4; i++)
#pragma unroll
        for (int j = 0; j < 4; j++) {
#pragma unroll
            for (int q = 0; q < 4; q++) acc[i][j][q] = 0.f;
            acc16[i][j][0] = 0u; acc16[i][j][1] = 0u;
        }

    float4 stP[8];

    // prologue: chunk 0
#pragma unroll
    for (int j = 0; j < 8; j++) {
        int row = j * 16 + r0;
        const void* src = &Asrc[((size_t)(b0 + row) * 64 + n) * K + ac * 8];
        CP_ASYNC16(sb + aregion + row * 128 + cswA, src);
    }
    CP_COMMIT();
#pragma unroll
    for (int j = 0; j < 8; j++) {
        int row = j * 16 + r0;
        stP[j] = *(const float4*)&Pw[((size_t)n * M + m0 + row) * K + c4 * 4];
    }
#pragma unroll
    for (int j = 0; j < 8; j++) {
        int row = j * 16 + r0;
        *(uint2*)(sm + 32768 + row * 128 + cswP) = cvt4h(stP[j]);
    }
    CP_WAIT0();
    __syncthreads();

    for (int c = 0; c < nchunk; c++) {
        if (c + 1 < nchunk) {
            int k0 = (c + 1) << 6;
            uint32_t bdst = sb + ((c + 1) & 1) * GBUF;
#pragma unroll
            for (int j = 0; j < 8; j++) {
                int row = j * 16 + r0;
                const void* src = &Asrc[((size_t)(b0 + row) * 64 + n) * K + k0 + ac * 8];
                CP_ASYNC16(bdst + aregion + row * 128 + cswA, src);
            }
            CP_COMMIT();
#pragma unroll
            for (int j = 0; j < 8; j++) {
                int row = j * 16 + r0;
                stP[j] = *(const float4*)&Pw[((size_t)n * M + m0 + row) * K + k0 + c4 * 4];
            }
        }

        uint32_t ub = sb + (c & 1) * GBUF;
#pragma unroll
        for (int kk = 0; kk < 4; kk++) {
            uint32_t ah[4][4], al[4][4], bh[2][4];
            int ksel = kk * 2 + kch;
#pragma unroll
            for (int mm = 0; mm < 4; mm++)
                ldmx4(ah[mm], ub + rowA128[mm] + ((ksel ^ r7A[mm]) << 4));
#pragma unroll
            for (int mm = 0; mm < 4; mm++)
                ldmx4(al[mm], ub + 16384 + rowA128[mm] + ((ksel ^ r7A[mm]) << 4));
#pragma unroll
            for (int g = 0; g < 2; g++)
                ldmx4(bh[g], ub + 32768 + rowB128[g] + ((ksel ^ r7B[g]) << 4));
#pragma unroll
            for (int mm = 0; mm < 4; mm++)
#pragma unroll
                for (int nn = 0; nn < 4; nn++) {
                    int g = nn >> 1, s = nn & 1;
                    mma_f16(acc[mm][nn], ah[mm], bh[g][s], bh[g][s + 2]);
                    mma_f16acc(acc16[mm][nn], al[mm], bh[g][s], bh[g][s + 2]);
                }
        }

        if (c + 1 < nchunk) {
            char* buf = sm + ((c + 1) & 1) * GBUF;
#pragma unroll
            for (int j = 0; j < 8; j++) {
                int row = j * 16 + r0;
                *(uint2*)(buf + 32768 + row * 128 + cswP) = cvt4h(stP[j]);
            }
            CP_WAIT0();
        }
        __syncthreads();
    }

    // merge f16 correction + relu
#pragma unroll
    for (int i = 0; i < 4; i++)
#pragma unroll
        for (int j = 0; j < 4; j++) {
            __half2 p0 = *reinterpret_cast<__half2*>(&acc16[i][j][0]);
            __half2 p1 = *reinterpret_cast<__half2*>(&acc16[i][j][1]);
            acc[i][j][0] += __low2float(p0);
            acc[i][j][1] += __high2float(p0);
            acc[i][j][2] += __low2float(p1);
            acc[i][j][3] += __high2float(p1);
        }
    if (relu) {
#pragma unroll
        for (int i = 0; i < 4; i++)
#pragma unroll
            for (int j = 0; j < 4; j++)
#pragma unroll
                for (int q = 0; q < 4; q++) acc[i][j][q] = fmaxf(acc[i][j][q], 0.f);
    }

#pragma unroll
    for (int mm = 0; mm < 4; mm++) {
        int bg = b0 + warp_b * 64 + mm * 16 + (lid >> 2);
#pragma unroll
        for (int nn = 0; nn < 4; nn++) {
            int og = m0 + warp_o * 32 + nn * 8 + (lid & 3) * 2;
            float2 v01 = make_float2(acc[mm][nn][0], acc[mm][nn][1]);
            float2 v23 = make_float2(acc[mm][nn][2], acc[mm][nn][3]);
            *(float2*)&Y[((size_t)n * 256 + bg) * M + og] = v01;
            *(float2*)&Y[((size_t)n * 256 + bg + 8) * M + og] = v23;
        }
    }

    // fused BN partial stats (deterministic per-slot)
    if (stats) {
        float s1[8], s2v[8];
#pragma unroll
        for (int k = 0; k < 8; k++) { s1[k] = 0.f; s2v[k] = 0.f; }
#pragma unroll
        for (int nn = 0; nn < 4; nn++)
#pragma unroll
            for (int q = 0; q < 2; q++) {
                int k = nn * 2 + q;
#pragma unroll
                for (int mm = 0; mm < 4; mm++) {
                    float v0 = acc[mm][nn][q], v1 = acc[mm][nn][q + 2];
                    s1[k] += v0 + v1;
                    s2v[k] += v0 * v0 + v1 * v1;
                }
            }
#pragma unroll
        for (int k = 0; k < 8; k++)
#pragma unroll
            for (int msk = 4; msk <= 16; msk <<= 1) {
                s1[k]  += __shfl_xor_sync(0xFFFFFFFFu, s1[k],  msk);
                s2v[k] += __shfl_xor_sync(0xFFFFFFFFu, s2v[k], msk);
            }
        if ((lid >> 2) == 0) {
            int slot = (by * 64 + n) * 2 + warp_b;
#pragma unroll
            for (int nn = 0; nn < 4; nn++)
#pragma unroll
                for (int q = 0; q < 2; q++) {
                    int ch = m0 + warp_o * 32 + nn * 8 + (lid & 3) * 2 + q;
                    g_pS [slot * CDIM + ch] = s1[nn * 2 + q];
                    g_pS2[slot * CDIM + ch] = s2v[nn * 2 + q];
                }
        }
    }
}

// ================= pre/post kernels =================
__global__ void build_a0(const float* __restrict__ Hre, const float* __restrict__ Him) {
    int b = blockIdx.x, t = threadIdx.x;
    const float* hr = Hre + (size_t)b * 2048;
    const float* hi = Him + (size_t)b * 2048;
    size_t dbase = (size_t)b * 4096;
#pragma unroll
    for (int j = 0; j < 8; j++) {
        int idx = t + j * 256;
        int n = idx >> 5, d = idx & 31;
        float v0 = hr[idx], v1 = hi[idx];
        __half h0 = __float2half_rn(v0);
        __half h1 = __float2half_rn(v1);
        g_A0h[dbase + n * 64 + d]      = h0;
        g_A0h[dbase + n * 64 + 32 + d] = h1;
        g_A0l[dbase + n * 64 + d]      = __float2half_rn(v0 - __half2float(h0));
        g_A0l[dbase + n * 64 + 32 + d] = __float2half_rn(v1 - __half2float(h1));
    }
}

// slot-parallel BN finalize: 32 blocks x 256 thr
__global__ void bn_finalize(const float* __restrict__ w, const float* __restrict__ bb) {
    int c = blockIdx.x * 32 + (threadIdx.x & 31);
    int g = threadIdx.x >> 5;
    float s = 0.f, s2 = 0.f;
#pragma unroll
    for (int i = 0; i < 32; i++) {
        int sl = g * 32 + i;
        s  += g_pS [sl * CDIM + c];
        s2 += g_pS2[sl * CDIM + c];
    }
    __shared__ float a1[8][32], a2[8][32];
    a1[g][threadIdx.x & 31] = s;
    a2[g][threadIdx.x & 31] = s2;
    __syncthreads();
    if (g == 0) {
        float ts = 0.f, ts2 = 0.f;
#pragma unroll
        for (int j = 0; j < 8; j++) { ts += a1[j][threadIdx.x & 31]; ts2 += a2[j][threadIdx.x & 31]; }
        float mean = ts / (float)BL;
        float var  = ts2 / (float)BL - mean * mean;
        float sc = w[c] * rsqrtf(var + 1e-5f);
        g_scale[c] = sc;
        g_shift[c] = bb[c] - mean * sc;
    }
}

// elementwise BN-apply: m -> Mh/Ml (fp16 hi/lo), softplus(std) -> S (fp32)
__global__ void bn_apply(const float* __restrict__ Y) {
    int nb = blockIdx.x, t = threadIdx.x;   // 128 threads
    int n = nb >> 8, b = nb & 255;
    size_t ybase = (size_t)nb * CDIM;
    size_t mbase = ((size_t)b * 64 + n) * HDIM;
    int d = t * 4;

    float4 ym = *(const float4*)&Y[ybase + d];
    float4 ys = *(const float4*)&Y[ybase + HDIM + d];
    float4 scm = *(const float4*)&g_scale[d];
    float4 shm = *(const float4*)&g_shift[d];
    float4 scs = *(const float4*)&g_scale[HDIM + d];
    float4 shs = *(const float4*)&g_shift[HDIM + d];

    float m[4] = { scm.x * ym.x + shm.x, scm.y * ym.y + shm.y,
                   scm.z * ym.z + shm.z, scm.w * ym.w + shm.w };
    float x[4] = { scs.x * ys.x + shs.x, scs.y * ys.y + shs.y,
                   scs.z * ys.z + shs.z, scs.w * ys.w + shs.w };
    float4 sv;
    float* sp = &sv.x;
    float lo[4];
#pragma unroll
    for (int i = 0; i < 4; i++) {
        sp[i] = fmaxf(x[i], 0.f) + log1pf(__expf(-fabsf(x[i]))) + 1e-10f;
        __half mh = __float2half_rn(m[i]);
        lo[i] = m[i] - __half2float(mh);
        m[i] = __half2float(mh);
    }
    __half2 mh01 = __floats2half2_rn(m[0], m[1]);
    __half2 mh23 = __floats2half2_rn(m[2], m[3]);
    __half2 ml01 = __floats2half2_rn(lo[0], lo[1]);
    __half2 ml23 = __floats2half2_rn(lo[2], lo[3]);
    uint2 hv, lv;
    hv.x = *reinterpret_cast<uint32_t*>(&mh01);
    hv.y = *reinterpret_cast<uint32_t*>(&mh23);
    lv.x = *reinterpret_cast<uint32_t*>(&ml01);
    lv.y = *reinterpret_cast<uint32_t*>(&ml23);
    *(uint2*)&g_Mh[mbase + d] = hv;
    *(uint2*)&g_Ml[mbase + d] = lv;
    *(float4*)&g_S[mbase + d] = sv;
}

// standalone noise-MI kernel (no smem config conflict -> full occupancy).
// Reads Mh/Ml/S of the layer just applied; runs on a forked stream.
__global__ void noise_mi(const float* __restrict__ Nz, int add) {
    int nb = blockIdx.x, t = threadIdx.x;   // 128 threads
    int n2 = nb >> 8, b2 = nb & 255;
    size_t bl = (size_t)b2 * 64 + n2;
    size_t mbase = bl * HDIM;
    int d = t * 4;

    uint2 hv = *(const uint2*)&g_Mh[mbase + d];
    uint2 lv = *(const uint2*)&g_Ml[mbase + d];
    float4 sv = *(const float4*)&g_S[mbase + d];
    float4 z0 = *(const float4*)&Nz[mbase + d];
    float4 z1 = *(const float4*)&Nz[mbase + d + NS_STRIDE];
    float4 z2 = *(const float4*)&Nz[mbase + d + 2 * NS_STRIDE];
    float4 z3 = *(const float4*)&Nz[mbase + d + 3 * NS_STRIDE];

    __half2 h01 = *reinterpret_cast<__half2*>(&hv.x);
    __half2 h23 = *reinterpret_cast<__half2*>(&hv.y);
    __half2 l01 = *reinterpret_cast<__half2*>(&lv.x);
    __half2 l23 = *reinterpret_cast<__half2*>(&lv.y);
    float m[4] = { __low2float(h01) + __low2float(l01),
                   __high2float(h01) + __high2float(l01),
                   __low2float(h23) + __low2float(l23),
                   __high2float(h23) + __high2float(l23) };
    float s[4] = { sv.x, sv.y, sv.z, sv.w };
    float a0[4] = { z0.x, z0.y, z0.z, z0.w };
    float a1[4] = { z1.x, z1.y, z1.z, z1.w };
    float a2[4] = { z2.x, z2.y, z2.z, z2.w };
    float a3[4] = { z3.x, z3.y, z3.z, z3.w };

    float local = 0.f;
#pragma unroll
    for (int i = 0; i < 4; i++) {
        float S1 = (a0[i] + a1[i] + a2[i] + a3[i]) * 0.25f;
        float S2 = (a0[i] * a0[i] + a1[i] * a1[i] +
                    a2[i] * a2[i] + a3[i] * a3[i]) * 0.25f;
        local += 0.5f * m[i] * m[i] - __logf(s[i]) + m[i] * s[i] * S1
               + 0.5f * (s[i] * s[i] - 1.0f) * S2;
    }
    __shared__ float sh[128];
    sh[t] = local;
    __syncthreads();
    for (int off = 64; off; off >>= 1) {
        if (t < off) sh[t] += sh[t + off];
        __syncthreads();
    }
    if (t == 0) {
        if (add) g_Ipart[bl] += sh[0];
        else     g_Ipart[bl]  = sh[0];
    }
}

// merged pn + final + I-sum
__global__ void epilogue_kernel(float* __restrict__ out) {
    int b = blockIdx.x, t = threadIdx.x;
    __shared__ float v[64][72];
    __shared__ float pk[64];
    __shared__ float Pn[8];
    __shared__ float mult[64][8];

    for (int idx = t; idx < 64 * 72; idx += 128) {
        int n = idx / 72, c = idx % 72;
        v[n][c] = g_Y2[((size_t)(n * 256 + b)) * MOUT + c];
    }
    __syncthreads();
    if (t < 64) {
        int k = t & 7, j = t >> 3;
        float s = 0.f;
#pragma unroll
        for (int n = j; n < 64; n += 8) { float x = v[n][64 + k]; s += x * x; }
        pk[t] = s;
    }
    __syncthreads();
    if (t < 8) {
        float tot = 0.f;
#pragma unroll
        for (int j = 0; j < 8; j++) tot += pk[j * 8 + t];
        Pn[t] = sqrtf(tot);
    }
    __syncthreads();
    for (int idx = t; idx < 512; idx += 128) {
        int n = idx >> 3, k = idx & 7;
        float ss = 0.f;
#pragma unroll
        for (int u = 0; u < 4; u++) {
            float a = v[n][k * 4 + u], c2 = v[n][32 + k * 4 + u];
            ss += a * a + c2 * c2;
        }
        mult[n][k] = v[n][64 + k] / Pn[k] * 8.0f / sqrtf(ss);  // sqrt(L)=8
    }
    __syncthreads();
    for (int idx = t; idx < 64 * 32; idx += 128) {
        int n = idx >> 5, c = idx & 31;
        size_t obase = ((size_t)b * 64 + n) * 32;
        float mlt = mult[n][c >> 2];
        out[OUT_FRE + obase + c] = v[n][c] * mlt;
        out[OUT_FIM + obase + c] = v[n][32 + c] * mlt;
    }
    if (t < 64) pk[t] = g_Ipart[(size_t)b * 64 + t];
    __syncthreads();
    if (t == 0) {
        float s = 0.f;
#pragma unroll
        for (int n = 0; n < 64; n++) s += pk[n];
        out[OUT_I + b] = s;
    }
}

// ================= launch =================
extern "C" void kernel_launch(void* const* d_in, const int* in_sizes, int n_in,
                              void* d_out, int out_size) {
    const float* Hre = (const float*)d_in[0];
    const float* Him = (const float*)d_in[1];
    const float* P0  = (const float*)d_in[2];
    const float* P1  = (const float*)d_in[3];
    const float* P2  = (const float*)d_in[4];
    const float* w0  = (const float*)d_in[5];
    const float* b0  = (const float*)d_in[6];
    const float* w1  = (const float*)d_in[7];
    const float* b1  = (const float*)d_in[8];
    const float* nz0 = (const float*)d_in[9];
    const float* nz1 = (const float*)d_in[10];
    float* out = (float*)d_out;

    float *Yp, *Y2p;
    __half *A0h, *A0l, *Mh, *Ml;
    cudaGetSymbolAddress((void**)&A0h, g_A0h);
    cudaGetSymbolAddress((void**)&A0l, g_A0l);
    cudaGetSymbolAddress((void**)&Yp,  g_Y);
    cudaGetSymbolAddress((void**)&Mh,  g_Mh);
    cudaGetSymbolAddress((void**)&Ml,  g_Ml);
    cudaGetSymbolAddress((void**)&Y2p, g_Y2);

    cudaFuncSetAttribute(gemm_mma, cudaFuncAttributeMaxDynamicSharedMemorySize, GSMEM);

    // Side stream + events: graph capture supports event-based forks; all
    // host-side objects (no device allocation). The noise kernels run on a
    // parallel graph branch with their own (smem-free) occupancy config.
    cudaStream_t s2;
    cudaStreamCreateWithFlags(&s2, cudaStreamNonBlocking);
    cudaEvent_t evFork0, evFork1, evN0, evN1;
    cudaEventCreateWithFlags(&evFork0, cudaEventDisableTiming);
    cudaEventCreateWithFlags(&evFork1, cudaEventDisableTiming);
    cudaEventCreateWithFlags(&evN0, cudaEventDisableTiming);
    cudaEventCreateWithFlags(&evN1, cudaEventDisableTiming);

    // layer 0: K=64
    build_a0<<<BDIM, 256>>>(Hre, Him);
    gemm_mma<<<1024, 256, GSMEM>>>(P0, A0h, A0l, Yp, DIN, CDIM, 1, 1, 8);
    bn_finalize<<<32, 256>>>(w0, b0);
    bn_apply<<<BL, 128>>>(Yp);

    // fork: noise0 reads layer-0 Mh/Ml/S concurrently with layer-1 gemm
    cudaEventRecord(evFork0, 0);
    cudaStreamWaitEvent(s2, evFork0, 0);
    noise_mi<<<BL, 128, 0, s2>>>(nz0, 0);
    cudaEventRecord(evN0, s2);

    // layer 1: K=512
    gemm_mma<<<1024, 256, GSMEM>>>(P1, Mh, Ml, Yp, HDIM, CDIM, 1, 1, 8);
    bn_finalize<<<32, 256>>>(w1, b1);
    cudaStreamWaitEvent(0, evN0, 0);      // WAR: apply1 overwrites Mh/Ml/S
    bn_apply<<<BL, 128>>>(Yp);

    // fork: noise1 concurrent with layer-2 gemm
    cudaEventRecord(evFork1, 0);
    cudaStreamWaitEvent(s2, evFork1, 0);
    noise_mi<<<BL, 128, 0, s2>>>(nz1, 1);
    cudaEventRecord(evN1, s2);

    // layer 2: K=512, channels 0..127 only
    gemm_mma<<<128, 256, GSMEM>>>(P2, Mh, Ml, Y2p, HDIM, MOUT, 0, 0, 1);

    // join: epilogue reads g_Ipart
    cudaStreamWaitEvent(0, evN1, 0);
    epilogue_kernel<<<BDIM, 128>>>(out);

    cudaEventDestroy(evFork0);
    cudaEventDestroy(evFork1);
    cudaEventDestroy(evN0);
    cudaEventDestroy(evN1);
    cudaStreamDestroy(s2);
}

// round 15
// speedup vs baseline: 1.4157x; 1.0048x over previous
#include <cuda_runtime.h>
#include <cuda_fp16.h>
#include <cstdint>

// Problem constants
#define BDIM  256          // B = BATCH*NBR
#define LDIM  64
#define DIN   64           // 2*K*U
#define HDIM  512
#define CDIM  1024         // 2*h
#define MOUT  144
#define BL    16384        // B*L
#define NS_STRIDE ((size_t)BL * HDIM)
#define OUT_FRE  0
#define OUT_FIM  524288
#define OUT_I    1048576

// ---------------- scratch ----------------
__device__ __align__(128) __half g_A0h[BDIM * LDIM * DIN];   // 2 MB
__device__ __align__(128) __half g_A0l[BDIM * LDIM * DIN];   // 2 MB
__device__ __align__(128) float g_Y [LDIM * BDIM * CDIM];    // 64 MB [n][b][o]
__device__ __align__(128) __half g_Mh[BL * HDIM];            // 16 MB [(b*64+n)][h]
__device__ __align__(128) __half g_Ml[BL * HDIM];            // 16 MB
__device__ __align__(128) float g_Y2[LDIM * BDIM * MOUT];    //  9 MB [n][b][c]
__device__ float g_pS [256 * CDIM];
__device__ float g_pS2[256 * CDIM];
__device__ float g_scale[CDIM];
__device__ float g_shift[CDIM];
__device__ float g_Ipart[BL];

// ================= helpers =================
__device__ __forceinline__ uint32_t smem_u32(const void* p) {
    uint32_t a;
    asm("{ .reg .u64 t; cvta.to.shared.u64 t, %1; cvt.u32.u64 %0, t; }" : "=r"(a) : "l"(p));
    return a;
}
__device__ __forceinline__ void ldmx4(uint32_t* r, uint32_t addr) {
    asm volatile("ldmatrix.sync.aligned.m8n8.x4.shared.b16 {%0,%1,%2,%3}, [%4];"
        : "=r"(r[0]), "=r"(r[1]), "=r"(r[2]), "=r"(r[3]) : "r"(addr));
}
__device__ __forceinline__ void mma_f16(float* c, const uint32_t* a,
                                        uint32_t b0, uint32_t b1) {
    asm volatile("mma.sync.aligned.m16n8k16.row.col.f32.f16.f16.f32 "
        "{%0,%1,%2,%3}, {%4,%5,%6,%7}, {%8,%9}, {%0,%1,%2,%3};"
        : "+f"(c[0]), "+f"(c[1]), "+f"(c[2]), "+f"(c[3])
        : "r"(a[0]), "r"(a[1]), "r"(a[2]), "r"(a[3]), "r"(b0), "r"(b1));
}
__device__ __forceinline__ void mma_f16acc(uint32_t* c, const uint32_t* a,
                                           uint32_t b0, uint32_t b1) {
    asm volatile("mma.sync.aligned.m16n8k16.row.col.f16.f16.f16.f16 "
        "{%0,%1}, {%2,%3,%4,%5}, {%6,%7}, {%0,%1};"
        : "+r"(c[0]), "+r"(c[1])
        : "r"(a[0]), "r"(a[1]), "r"(a[2]), "r"(a[3]), "r"(b0), "r"(b1));
}
#define CP_ASYNC16(dst, src) \
    asm volatile("cp.async.ca.shared.global [%0], [%1], 16;" :: "r"(dst), "l"(src))
#define CP_COMMIT() asm volatile("cp.async.commit_group;")
#define CP_WAIT0()  asm volatile("cp.async.wait_group 0;")

__device__ __forceinline__ uint2 cvt4h(float4 v) {
    __half2 a = __floats2half2_rn(v.x, v.y);
    __half2 b = __floats2half2_rn(v.z, v.w);
    uint2 r;
    r.x = *reinterpret_cast<uint32_t*>(&a);
    r.y = *reinterpret_cast<uint32_t*>(&b);
    return r;
}

// ================= tensor-core batched GEMM =================
// 2-term fp16: Ph*Ahi (f32 acc) + Ph*Alo (f16 acc)
// Y[n][b][o] = sum_d P[n][o][d] * Act[(b*64+n)][d]
// CTA tile 128b x 128o x 64k; 8 warps (2b x 4o).
// __launch_bounds__(256, 2): cap regs at 128/thr so 2 CTAs/SM are resident
// (R14 analysis: 1 CTA/SM made the gemm latency-bound at ~50% of pipe).
// P staged as converted fp16 (uint2[8], 16 regs) instead of float4[8] (32).
#define GBUF 49152
#define GSMEM (2 * GBUF)

__global__ __launch_bounds__(256, 2) void gemm_mma(
    const float* __restrict__ Pw,
    const __half* __restrict__ Ah, const __half* __restrict__ Al,
    float* __restrict__ Y, int K, int M, int relu, int stats, int mTiles)
{
    extern __shared__ char sm[];
    const int bid = blockIdx.x;
    const int tid = threadIdx.x;
    const int wid = tid >> 5, lid = tid & 31;
    const int m0 = (bid % mTiles) * 128;
    const int rem = bid / mTiles;
    const int by = rem & 1;
    const int n = rem >> 1;
    const int b0 = by * 128;
    const int nchunk = K >> 6;
    uint32_t sb = smem_u32(sm);

    const int r0 = tid >> 4, c4 = tid & 15;
    const int cswP = (((c4 >> 1) ^ (r0 & 7)) << 4) + (c4 & 1) * 8;
    const int ac = c4 & 7;
    const int aregion = (c4 < 8) ? 0 : 16384;
    const int cswA = ((ac ^ (r0 & 7)) << 4);
    const __half* Asrc = (c4 < 8) ? Ah : Al;

    const int lr  = (lid & 7) + ((lid >> 3) & 1) * 8;
    const int kch = lid >> 4;
    const int warp_b = wid >> 2, warp_o = wid & 3;
    int rowA128[4], r7A[4], rowB128[2], r7B[2];
#pragma unroll
    for (int mm = 0; mm < 4; mm++) {
        int r = warp_b * 64 + mm * 16 + lr;
        rowA128[mm] = r * 128; r7A[mm] = r & 7;
    }
#pragma unroll
    for (int g = 0; g < 2; g++) {
        int r = warp_o * 32 + g * 16 + lr;
        rowB128[g] = r * 128; r7B[g] = r & 7;
    }

    float acc[4][4][4];
    uint32_t acc16[4][4][2];
#pragma unroll
    for (int i = 0; i < 4; i++)
#pragma unroll
        for (int j = 0; j < 4; j++) {
#pragma unroll
            for (int q = 0; q < 4; q++) acc[i][j][q] = 0.f;
            acc16[i][j][0] = 0u; acc16[i][j][1] = 0u;
        }

    uint2 stPh[8];   // P staged post-conversion (16 regs, not 32)

    // prologue: chunk 0
#pragma unroll
    for (int j = 0; j < 8; j++) {
        int row = j * 16 + r0;
        const void* src = &Asrc[((size_t)(b0 + row) * 64 + n) * K + ac * 8];
        CP_ASYNC16(sb + aregion + row * 128 + cswA, src);
    }
    CP_COMMIT();
#pragma unroll
    for (int j = 0; j < 8; j++) {
        int row = j * 16 + r0;
        stPh[j] = cvt4h(*(const float4*)&Pw[((size_t)n * M + m0 + row) * K + c4 * 4]);
    }
#pragma unroll
    for (int j = 0; j < 8; j++) {
        int row = j * 16 + r0;
        *(uint2*)(sm + 32768 + row * 128 + cswP) = stPh[j];
    }
    CP_WAIT0();
    __syncthreads();

    for (int c = 0; c < nchunk; c++) {
        if (c + 1 < nchunk) {
            int k0 = (c + 1) << 6;
            uint32_t bdst = sb + ((c + 1) & 1) * GBUF;
#pragma unroll
            for (int j = 0; j < 8; j++) {
                int row = j * 16 + r0;
                const void* src = &Asrc[((size_t)(b0 + row) * 64 + n) * K + k0 + ac * 8];
                CP_ASYNC16(bdst + aregion + row * 128 + cswA, src);
            }
            CP_COMMIT();
#pragma unroll
            for (int j = 0; j < 8; j++) {
                int row = j * 16 + r0;
                stPh[j] = cvt4h(*(const float4*)&Pw[((size_t)n * M + m0 + row) * K + k0 + c4 * 4]);
            }
        }

        uint32_t ub = sb + (c & 1) * GBUF;
#pragma unroll
        for (int kk = 0; kk < 4; kk++) {
            uint32_t ah[4][4], al[4][4], bh[2][4];
            int ksel = kk * 2 + kch;
#pragma unroll
            for (int mm = 0; mm < 4; mm++)
                ldmx4(ah[mm], ub + rowA128[mm] + ((ksel ^ r7A[mm]) << 4));
#pragma unroll
            for (int mm = 0; mm < 4; mm++)
                ldmx4(al[mm], ub + 16384 + rowA128[mm] + ((ksel ^ r7A[mm]) << 4));
#pragma unroll
            for (int g = 0; g < 2; g++)
                ldmx4(bh[g], ub + 32768 + rowB128[g] + ((ksel ^ r7B[g]) << 4));
#pragma unroll
            for (int mm = 0; mm < 4; mm++)
#pragma unroll
                for (int nn = 0; nn < 4; nn++) {
                    int g = nn >> 1, s = nn & 1;
                    mma_f16(acc[mm][nn], ah[mm], bh[g][s], bh[g][s + 2]);
                    mma_f16acc(acc16[mm][nn], al[mm], bh[g][s], bh[g][s + 2]);
                }
        }

        if (c + 1 < nchunk) {
            char* buf = sm + ((c + 1) & 1) * GBUF;
#pragma unroll
            for (int j = 0; j < 8; j++) {
                int row = j * 16 + r0;
                *(uint2*)(buf + 32768 + row * 128 + cswP) = stPh[j];
            }
            CP_WAIT0();
        }
        __syncthreads();
    }

    // merge f16 correction + relu
#pragma unroll
    for (int i = 0; i < 4; i++)
#pragma unroll
        for (int j = 0; j < 4; j++) {
            __half2 p0 = *reinterpret_cast<__half2*>(&acc16[i][j][0]);
            __half2 p1 = *reinterpret_cast<__half2*>(&acc16[i][j][1]);
            acc[i][j][0] += __low2float(p0);
            acc[i][j][1] += __high2float(p0);
            acc[i][j][2] += __low2float(p1);
            acc[i][j][3] += __high2float(p1);
        }
    if (relu) {
#pragma unroll
        for (int i = 0; i < 4; i++)
#pragma unroll
            for (int j = 0; j < 4; j++)
#pragma unroll
                for (int q = 0; q < 4; q++) acc[i][j][q] = fmaxf(acc[i][j][q], 0.f);
    }

#pragma unroll
    for (int mm = 0; mm < 4; mm++) {
        int bg = b0 + warp_b * 64 + mm * 16 + (lid >> 2);
#pragma unroll
        for (int nn = 0; nn < 4; nn++) {
            int og = m0 + warp_o * 32 + nn * 8 + (lid & 3) * 2;
            float2 v01 = make_float2(acc[mm][nn][0], acc[mm][nn][1]);
            float2 v23 = make_float2(acc[mm][nn][2], acc[mm][nn][3]);
            *(float2*)&Y[((size_t)n * 256 + bg) * M + og] = v01;
            *(float2*)&Y[((size_t)n * 256 + bg + 8) * M + og] = v23;
        }
    }

    // fused BN partial stats (deterministic per-slot)
    if (stats) {
        float s1[8], s2v[8];
#pragma unroll
        for (int k = 0; k < 8; k++) { s1[k] = 0.f; s2v[k] = 0.f; }
#pragma unroll
        for (int nn = 0; nn < 4; nn++)
#pragma unroll
            for (int q = 0; q < 2; q++) {
                int k = nn * 2 + q;
#pragma unroll
                for (int mm = 0; mm < 4; mm++) {
                    float v0 = acc[mm][nn][q], v1 = acc[mm][nn][q + 2];
                    s1[k] += v0 + v1;
                    s2v[k] += v0 * v0 + v1 * v1;
                }
            }
#pragma unroll
        for (int k = 0; k < 8; k++)
#pragma unroll
            for (int msk = 4; msk <= 16; msk <<= 1) {
                s1[k]  += __shfl_xor_sync(0xFFFFFFFFu, s1[k],  msk);
                s2v[k] += __shfl_xor_sync(0xFFFFFFFFu, s2v[k], msk);
            }
        if ((lid >> 2) == 0) {
            int slot = (by * 64 + n) * 2 + warp_b;
#pragma unroll
            for (int nn = 0; nn < 4; nn++)
#pragma unroll
                for (int q = 0; q < 2; q++) {
                    int ch = m0 + warp_o * 32 + nn * 8 + (lid & 3) * 2 + q;
                    g_pS [slot * CDIM + ch] = s1[nn * 2 + q];
                    g_pS2[slot * CDIM + ch] = s2v[nn * 2 + q];
                }
        }
    }
}

// ================= pre/post kernels =================
__global__ void build_a0(const float* __restrict__ Hre, const float* __restrict__ Him) {
    int b = blockIdx.x, t = threadIdx.x;
    const float* hr = Hre + (size_t)b * 2048;
    const float* hi = Him + (size_t)b * 2048;
    size_t dbase = (size_t)b * 4096;
#pragma unroll
    for (int j = 0; j < 8; j++) {
        int idx = t + j * 256;
        int n = idx >> 5, d = idx & 31;
        float v0 = hr[idx], v1 = hi[idx];
        __half h0 = __float2half_rn(v0);
        __half h1 = __float2half_rn(v1);
        g_A0h[dbase + n * 64 + d]      = h0;
        g_A0h[dbase + n * 64 + 32 + d] = h1;
        g_A0l[dbase + n * 64 + d]      = __float2half_rn(v0 - __half2float(h0));
        g_A0l[dbase + n * 64 + 32 + d] = __float2half_rn(v1 - __half2float(h1));
    }
}

// slot-parallel BN finalize: 32 blocks x 256 thr
__global__ void bn_finalize(const float* __restrict__ w, const float* __restrict__ bb) {
    int c = blockIdx.x * 32 + (threadIdx.x & 31);
    int g = threadIdx.x >> 5;
    float s = 0.f, s2 = 0.f;
#pragma unroll
    for (int i = 0; i < 32; i++) {
        int sl = g * 32 + i;
        s  += g_pS [sl * CDIM + c];
        s2 += g_pS2[sl * CDIM + c];
    }
    __shared__ float a1[8][32], a2[8][32];
    a1[g][threadIdx.x & 31] = s;
    a2[g][threadIdx.x & 31] = s2;
    __syncthreads();
    if (g == 0) {
        float ts = 0.f, ts2 = 0.f;
#pragma unroll
        for (int j = 0; j < 8; j++) { ts += a1[j][threadIdx.x & 31]; ts2 += a2[j][threadIdx.x & 31]; }
        float mean = ts / (float)BL;
        float var  = ts2 / (float)BL - mean * mean;
        float sc = w[c] * rsqrtf(var + 1e-5f);
        g_scale[c] = sc;
        g_shift[c] = bb[c] - mean * sc;
    }
}

// fused BN-apply + softplus + closed-form noise MI (R10-proven)
__global__ void bn_noise(const float* __restrict__ Y, const float* __restrict__ Nz, int add) {
    int nb = blockIdx.x, t = threadIdx.x;   // 128 threads
    int n = nb >> 8, b = nb & 255;
    size_t ybase = (size_t)nb * CDIM;
    size_t bl = (size_t)b * 64 + n;
    size_t mbase = bl * HDIM;
    int d = t * 4;

    float4 ym = *(const float4*)&Y[ybase + d];
    float4 ys = *(const float4*)&Y[ybase + HDIM + d];
    float4 scm = *(const float4*)&g_scale[d];
    float4 shm = *(const float4*)&g_shift[d];
    float4 scs = *(const float4*)&g_scale[HDIM + d];
    float4 shs = *(const float4*)&g_shift[HDIM + d];
    float4 n0 = *(const float4*)&Nz[mbase + d];
    float4 n1 = *(const float4*)&Nz[mbase + d + NS_STRIDE];
    float4 n2 = *(const float4*)&Nz[mbase + d + 2 * NS_STRIDE];
    float4 n3 = *(const float4*)&Nz[mbase + d + 3 * NS_STRIDE];

    float m[4] = { scm.x * ym.x + shm.x, scm.y * ym.y + shm.y,
                   scm.z * ym.z + shm.z, scm.w * ym.w + shm.w };
    float x[4] = { scs.x * ys.x + shs.x, scs.y * ys.y + shs.y,
                   scs.z * ys.z + shs.z, scs.w * ys.w + shs.w };
    float nn0[4] = { n0.x, n0.y, n0.z, n0.w };
    float nn1[4] = { n1.x, n1.y, n1.z, n1.w };
    float nn2[4] = { n2.x, n2.y, n2.z, n2.w };
    float nn3[4] = { n3.x, n3.y, n3.z, n3.w };

    float local = 0.f;
    float lo[4];
#pragma unroll
    for (int i = 0; i < 4; i++) {
        float s = fmaxf(x[i], 0.f) + log1pf(__expf(-fabsf(x[i]))) + 1e-10f;
        float S1 = (nn0[i] + nn1[i] + nn2[i] + nn3[i]) * 0.25f;
        float S2 = (nn0[i] * nn0[i] + nn1[i] * nn1[i] +
                    nn2[i] * nn2[i] + nn3[i] * nn3[i]) * 0.25f;
        local += 0.5f * m[i] * m[i] - __logf(s) + m[i] * s * S1
               + 0.5f * (s * s - 1.0f) * S2;
        __half mh = __float2half_rn(m[i]);
        lo[i] = m[i] - __half2float(mh);
        m[i] = __half2float(mh);
    }
    __half2 mh01 = __floats2half2_rn(m[0], m[1]);
    __half2 mh23 = __floats2half2_rn(m[2], m[3]);
    __half2 ml01 = __floats2half2_rn(lo[0], lo[1]);
    __half2 ml23 = __floats2half2_rn(lo[2], lo[3]);
    uint2 hv, lv;
    hv.x = *reinterpret_cast<uint32_t*>(&mh01);
    hv.y = *reinterpret_cast<uint32_t*>(&mh23);
    lv.x = *reinterpret_cast<uint32_t*>(&ml01);
    lv.y = *reinterpret_cast<uint32_t*>(&ml23);
    *(uint2*)&g_Mh[mbase + d] = hv;
    *(uint2*)&g_Ml[mbase + d] = lv;

    __shared__ float sh[128];
    sh[t] = local;
    __syncthreads();
    for (int off = 64; off; off >>= 1) {
        if (t < off) sh[t] += sh[t + off];
        __syncthreads();
    }
    if (t == 0) {
        if (add) g_Ipart[bl] += sh[0];
        else     g_Ipart[bl]  = sh[0];
    }
}

// merged pn + final + I-sum
__global__ void epilogue_kernel(float* __restrict__ out) {
    int b = blockIdx.x, t = threadIdx.x;
    __shared__ float v[64][72];
    __shared__ float pk[64];
    __shared__ float Pn[8];
    __shared__ float mult[64][8];

    for (int idx = t; idx < 64 * 72; idx += 128) {
        int n = idx / 72, c = idx % 72;
        v[n][c] = g_Y2[((size_t)(n * 256 + b)) * MOUT + c];
    }
    __syncthreads();
    if (t < 64) {
        int k = t & 7, j = t >> 3;
        float s = 0.f;
#pragma unroll
        for (int n = j; n < 64; n += 8) { float x = v[n][64 + k]; s += x * x; }
        pk[t] = s;
    }
    __syncthreads();
    if (t < 8) {
        float tot = 0.f;
#pragma unroll
        for (int j = 0; j < 8; j++) tot += pk[j * 8 + t];
        Pn[t] = sqrtf(tot);
    }
    __syncthreads();
    for (int idx = t; idx < 512; idx += 128) {
        int n = idx >> 3, k = idx & 7;
        float ss = 0.f;
#pragma unroll
        for (int u = 0; u < 4; u++) {
            float a = v[n][k * 4 + u], c2 = v[n][32 + k * 4 + u];
            ss += a * a + c2 * c2;
        }
        mult[n][k] = v[n][64 + k] / Pn[k] * 8.0f / sqrtf(ss);  // sqrt(L)=8
    }
    __syncthreads();
    for (int idx = t; idx < 64 * 32; idx += 128) {
        int n = idx >> 5, c = idx & 31;
        size_t obase = ((size_t)b * 64 + n) * 32;
        float mlt = mult[n][c >> 2];
        out[OUT_FRE + obase + c] = v[n][c] * mlt;
        out[OUT_FIM + obase + c] = v[n][32 + c] * mlt;
    }
    if (t < 64) pk[t] = g_Ipart[(size_t)b * 64 + t];
    __syncthreads();
    if (t == 0) {
        float s = 0.f;
#pragma unroll
        for (int n = 0; n < 64; n++) s += pk[n];
        out[OUT_I + b] = s;
    }
}

// ================= launch =================
extern "C" void kernel_launch(void* const* d_in, const int* in_sizes, int n_in,
                              void* d_out, int out_size) {
    const float* Hre = (const float*)d_in[0];
    const float* Him = (const float*)d_in[1];
    const float* P0  = (const float*)d_in[2];
    const float* P1  = (const float*)d_in[3];
    const float* P2  = (const float*)d_in[4];
    const float* w0  = (const float*)d_in[5];
    const float* b0  = (const float*)d_in[6];
    const float* w1  = (const float*)d_in[7];
    const float* b1  = (const float*)d_in[8];
    const float* nz0 = (const float*)d_in[9];
    const float* nz1 = (const float*)d_in[10];
    float* out = (float*)d_out;

    float *Yp, *Y2p;
    __half *A0h, *A0l, *Mh, *Ml;
    cudaGetSymbolAddress((void**)&A0h, g_A0h);
    cudaGetSymbolAddress((void**)&A0l, g_A0l);
    cudaGetSymbolAddress((void**)&Yp,  g_Y);
    cudaGetSymbolAddress((void**)&Mh,  g_Mh);
    cudaGetSymbolAddress((void**)&Ml,  g_Ml);
    cudaGetSymbolAddress((void**)&Y2p, g_Y2);

    cudaFuncSetAttribute(gemm_mma, cudaFuncAttributeMaxDynamicSharedMemorySize, GSMEM);

    // layer 0: K=64
    build_a0<<<BDIM, 256>>>(Hre, Him);
    gemm_mma<<<1024, 256, GSMEM>>>(P0, A0h, A0l, Yp, DIN, CDIM, 1, 1, 8);
    bn_finalize<<<32, 256>>>(w0, b0);
    bn_noise<<<BL, 128>>>(Yp, nz0, 0);

    // layer 1: K=512
    gemm_mma<<<1024, 256, GSMEM>>>(P1, Mh, Ml, Yp, HDIM, CDIM, 1, 1, 8);
    bn_finalize<<<32, 256>>>(w1, b1);
    bn_noise<<<BL, 128>>>(Yp, nz1, 1);

    // layer 2: K=512, channels 0..127 only
    gemm_mma<<<128, 256, GSMEM>>>(P2, Mh, Ml, Y2p, HDIM, MOUT, 0, 0, 1);

    // merged epilogue
    epilogue_kernel<<<BDIM, 128>>>(out);
}